// round 16
// baseline (speedup 1.0000x reference)
#include <cuda_runtime.h>
#include <cuda_fp16.h>
#include <cstdint>
#include <math.h>

// Problem constants
#define NB 16384
#define NC 5
#define NH 256
#define NV 512
#define NCV 2560
#define NBH 4194304
#define NBCV 41943040u
#define TINYF 1.17549435082228751e-38f

// ---------------- scratch (static device globals) ----------------
__device__ __half g_A[(size_t)NB * NCV];     // one-hot v fp16 (A for sample_h), k = c*512+v
__device__ __half g_hb[(size_t)NB * NH];     // h fp16 (A for sample_v, K=256)
__device__ __half g_Wv2[2][NCV * NH];        // [split][v*5+c][h]   (B for sample_v)
__device__ __half g_Wh2[2][NH * NCV];        // [split][h][c*512+v] (B for sample_h)
__device__ float  g_gn[NBCV];                // precomputed gumbel noise for next categorical

// ---------------- threefry2x32 (bit-exact with JAX, partitionable) ----------------
__host__ __device__ __forceinline__ uint32_t rotl32(uint32_t x, int r) {
#ifdef __CUDA_ARCH__
    return __funnelshift_l(x, x, r);
#else
    return (x << r) | (x >> (32 - r));
#endif
}

__host__ __device__ inline void threefry(uint32_t k0, uint32_t k1,
                                         uint32_t x0, uint32_t x1,
                                         uint32_t& o0, uint32_t& o1) {
    uint32_t k2 = k0 ^ k1 ^ 0x1BD11BDAu;
#define TFR(r) { x0 += x1; x1 = rotl32(x1, (r)); x1 ^= x0; }
    x0 += k0; x1 += k1;
    TFR(13) TFR(15) TFR(26) TFR(6)   x0 += k1; x1 += k2 + 1u;
    TFR(17) TFR(29) TFR(16) TFR(24)  x0 += k2; x1 += k0 + 2u;
    TFR(13) TFR(15) TFR(26) TFR(6)   x0 += k0; x1 += k1 + 3u;
    TFR(17) TFR(29) TFR(16) TFR(24)  x0 += k1; x1 += k2 + 4u;
    TFR(13) TFR(15) TFR(26) TFR(6)   x0 += k2; x1 += k0 + 5u;
#undef TFR
    o0 = x0; o1 = x1;
}

__device__ __forceinline__ uint32_t rand_bits(uint32_t k0, uint32_t k1, uint32_t i) {
    uint32_t a, b;
    threefry(k0, k1, 0u, i, a, b);
    return a ^ b;
}

__device__ __forceinline__ float bits_to_unit(uint32_t bits) {
    return __fadd_rn(__uint_as_float((bits >> 9) | 0x3f800000u), -1.0f);
}

// ---------------- small helpers ----------------
__device__ __forceinline__ uint32_t smem_u32(const void* p) {
    uint32_t a;
    asm("{ .reg .u64 t; cvta.to.shared.u64 t, %1; cvt.u32.u64 %0, t; }" : "=r"(a) : "l"(p));
    return a;
}

__device__ __forceinline__ void cp16(uint32_t s, const void* g) {
    asm volatile("cp.async.cg.shared.global [%0], [%1], 16;" :: "r"(s), "l"(g));
}
#define CP_COMMIT() asm volatile("cp.async.commit_group;" ::: "memory")
#define CP_WAIT(n)  asm volatile("cp.async.wait_group %0;" :: "n"(n) : "memory")

__device__ __forceinline__ void ldmx4(uint32_t* r, uint32_t addr) {
    asm volatile("ldmatrix.sync.aligned.m8n8.x4.shared.b16 {%0,%1,%2,%3}, [%4];"
                 : "=r"(r[0]), "=r"(r[1]), "=r"(r[2]), "=r"(r[3]) : "r"(addr));
}

__device__ __forceinline__ void mma16816(float* c, const uint32_t* a,
                                         uint32_t b0, uint32_t b1) {
    asm volatile(
        "mma.sync.aligned.m16n8k16.row.col.f32.f16.f16.f32 "
        "{%0,%1,%2,%3}, {%4,%5,%6,%7}, {%8,%9}, {%0,%1,%2,%3};"
        : "+f"(c[0]), "+f"(c[1]), "+f"(c[2]), "+f"(c[3])
        : "r"(a[0]), "r"(a[1]), "r"(a[2]), "r"(a[3]), "r"(b0), "r"(b1));
}

// ---------------- prep kernels ----------------
__device__ __forceinline__ void split2h(float w, __half& a, __half& b) {
    a = __float2half_rn(w);
    float r1 = w - __half2float(a);
    b = __float2half_rn(r1);
}

// g_Wv2: row index = v*5 + c (argmax-self-contained 80-col tiles)
__global__ void k_prep_wv(const float* __restrict__ W) {
    int i = blockIdx.x * 256 + threadIdx.x;   // over NCV*NH
    int h = i & (NH - 1);
    int row = i >> 8;                         // v*5 + c
    int c = row % NC;
    int v = row / NC;
    __half a, b;
    split2h(W[((size_t)(c * NH + h)) * NV + v], a, b);
    g_Wv2[0][i] = a; g_Wv2[1][i] = b;
}

// g_Wh2: [split][h][cv = c*512+v]
__global__ void k_prep_wh(const float* __restrict__ W) {
    int cv = blockIdx.x * 256 + threadIdx.x;  // 0..2559
    int h  = blockIdx.y;
    int v = cv & (NV - 1);
    int c = cv >> 9;
    __half a, b;
    split2h(W[((size_t)(c * NH + h)) * NV + v], a, b);
    size_t o = (size_t)h * NCV + cv;
    g_Wh2[0][o] = a; g_Wh2[1][o] = b;
}

// g_A = fp16(v0)  (v0 is exact one-hot; layout identical, k = c*512+v)
__global__ void k_cast_A0(const float* __restrict__ v0) {
    size_t i = ((size_t)blockIdx.x * 256 + threadIdx.x) * 4;
    float4 f = *(const float4*)(v0 + i);
    __half o[4] = {__float2half_rn(f.x), __float2half_rn(f.y),
                   __float2half_rn(f.z), __float2half_rn(f.w)};
    *(uint2*)(g_A + i) = *(uint2*)o;
}

// ---------------- shared tiling constants ----------------
#define BM 128
#define BK 32
#define ROWB 80                       // 32 fp16 (64B) + 16B pad -> conflict-free ldmatrix
#define ATILE (BM * ROWB)             // 10240
#define BSPLIT ((size_t)NCV * NH)

// ======================= sample_h GEMM (BN=64) + gumbel precompute =======================
#define BN 64
#define BTILE (BN * ROWB)             // 5120
#define STG (ATILE + 2 * BTILE)       // 20480
#define SMEMB (3 * STG)               // 61440

// GN=1: additionally compute 4 gumbel values per thread per chunk into g_gn
// using keys (gk0, gk1) -- for the NEXT categorical step.
template<int GN>
__global__ __launch_bounds__(256, 3)
void k_mma_h(const __half* __restrict__ Asrc,
             const __half* __restrict__ Bsrc,
             uint32_t key0, uint32_t key1,
             uint32_t gk0, uint32_t gk1,
             const float* __restrict__ cvec,
             float* __restrict__ fout) {
    extern __shared__ char smem[];
    const uint32_t sb = smem_u32(smem);
    const int tid = threadIdx.x;
    const int lane = tid & 31;
    const int wid = tid >> 5;
    const int wm = wid & 3;
    const int wn = wid >> 2;
    const int bn = blockIdx.x * BN;
    const int bm = blockIdx.y * BM;
    const int nk = NCV / BK;           // 80
    const uint32_t bid = blockIdx.y * gridDim.x + blockIdx.x;   // 0..511

    const int ar0 = tid >> 2;
    const int ac  = (tid & 3) * 16;
    const int ack = (tid & 3) * 8;
    const int br  = tid >> 2;

    const uint32_t aoff = (uint32_t)((wm * 32 + (lane & 15)) * ROWB + (lane >> 4) * 16);
    const uint32_t boff = (uint32_t)((wn * 32 + (lane & 7) + ((lane >> 4) << 3)) * ROWB
                                     + ((lane >> 3) & 1) * 16);

    auto issue = [&](int kc) {
        const int k0 = kc * BK;
        uint32_t s = sb + (kc % 3) * STG;
        cp16(s + ar0 * ROWB + ac,        Asrc + (size_t)(bm + ar0) * NCV + k0 + ack);
        cp16(s + (ar0 + 64) * ROWB + ac, Asrc + (size_t)(bm + ar0 + 64) * NCV + k0 + ack);
#pragma unroll
        for (int sp = 0; sp < 2; sp++)
            cp16(s + ATILE + sp * BTILE + br * ROWB + ac,
                 Bsrc + sp * BSPLIT + (size_t)(bn + br) * NCV + k0 + ack);
    };

    float acc[2][4][4];
#pragma unroll
    for (int i = 0; i < 2; i++)
#pragma unroll
        for (int j = 0; j < 4; j++)
#pragma unroll
            for (int q = 0; q < 4; q++) acc[i][j][q] = 0.0f;

    issue(0); CP_COMMIT();
    issue(1); CP_COMMIT();

#pragma unroll 1
    for (int kc = 0; kc < nk; kc++) {
        CP_WAIT(1);
        __syncthreads();
        if (kc + 2 < nk) issue(kc + 2);
        CP_COMMIT();

        const uint32_t sA = sb + (kc % 3) * STG;
        const uint32_t sB = sA + ATILE;

#pragma unroll
        for (int ks = 0; ks < 2; ks++) {
            uint32_t a[2][4];
#pragma unroll
            for (int mi = 0; mi < 2; mi++)
                ldmx4(a[mi], sA + aoff + (uint32_t)(mi * 16 * ROWB + ks * 32));
#pragma unroll
            for (int sp = 0; sp < 2; sp++) {
                uint32_t b[2][4];
#pragma unroll
                for (int nh = 0; nh < 2; nh++)
                    ldmx4(b[nh], sB + sp * BTILE + boff
                                 + (uint32_t)(nh * 16 * ROWB + ks * 32));
#pragma unroll
                for (int nh = 0; nh < 2; nh++)
#pragma unroll
                    for (int mi = 0; mi < 2; mi++) {
                        mma16816(acc[mi][nh * 2 + 0], a[mi], b[nh][0], b[nh][1]);
                        mma16816(acc[mi][nh * 2 + 1], a[mi], b[nh][2], b[nh][3]);
                    }
            }
        }

        // --- gumbel precompute: 4 values/thread/chunk, coalesced float4 store ---
        if (GN) {
            uint32_t jb = ((bid * 80u + (uint32_t)kc) << 10) + (uint32_t)tid * 4u;
            float4 gv;
#pragma unroll
            for (int q = 0; q < 4; q++) {
                float u = bits_to_unit(rand_bits(gk0, gk1, jb + q));
                float up = fmaxf(__fadd_rn(u, TINYF), TINYF);
                ((float*)&gv)[q] = -logf(-logf(up));
            }
            *(float4*)(g_gn + jb) = gv;
        }
    }

    // epilogue: sigmoid + threefry bernoulli
    const int r4 = lane >> 2;
    const int c2 = (lane & 3) * 2;
#pragma unroll
    for (int mi = 0; mi < 2; mi++) {
#pragma unroll
        for (int ni = 0; ni < 4; ni++) {
            const float* c = acc[mi][ni];
            const int col = bn + wn * 32 + ni * 8 + c2;
            const int row = bm + wm * 32 + mi * 16 + r4;
            const float cv0 = cvec[col], cv1 = cvec[col + 1];
#pragma unroll
            for (int half_ = 0; half_ < 2; half_++) {
                const int rr = row + half_ * 8;
                float x0 = __fadd_rn(c[half_ * 2 + 0], cv0);
                float x1 = __fadd_rn(c[half_ * 2 + 1], cv1);
                float p0 = __fadd_rn(__fmul_rn(0.5f, tanhf(__fmul_rn(0.5f, x0))), 0.5f);
                float p1 = __fadd_rn(__fmul_rn(0.5f, tanhf(__fmul_rn(0.5f, x1))), 0.5f);
                uint32_t gi = (uint32_t)rr * NH + col;
                float u0 = bits_to_unit(rand_bits(key0, key1, gi));
                float u1 = bits_to_unit(rand_bits(key0, key1, gi + 1));
                uint32_t b0 = (u0 < p0) ? 0x3C00u : 0u;
                uint32_t b1 = (u1 < p1) ? 0x3C00u : 0u;
                *(uint32_t*)(g_hb + (size_t)rr * NH + col) = (b1 << 16) | b0;
                if (fout)
                    *(float2*)(fout + (size_t)rr * NH + col) =
                        make_float2(b0 ? 1.0f : 0.0f, b1 ? 1.0f : 0.0f);
            }
        }
    }
}

// ============ sample_v GEMM + fused categorical (gumbel noise preloaded) ============
#define BNV 80
#define BTILEV (BNV * ROWB)            // 6400
#define STGV (ATILE + 2 * BTILEV)      // 23040
#define SMEMV (3 * STGV)               // 69120
#define TS 84

template<int WRITE_OUT>
__global__ __launch_bounds__(256, 3)
void k_mma_v(const __half* __restrict__ Asrc,   // g_hb, lda = NH
             const __half* __restrict__ Bsrc,   // g_Wv2, rows v*5+c, ldb = NH
             const float* __restrict__ bvec,
             float* __restrict__ vout) {
    extern __shared__ char smem[];
    const uint32_t sb = smem_u32(smem);
    float* tile = (float*)smem;
    const int tid = threadIdx.x;
    const int lane = tid & 31;
    const int wid = tid >> 5;          // 8 warps, each M=16 rows, full N=80
    const int bn = blockIdx.x * BNV;
    const int bm = blockIdx.y * BM;
    const int nk = NH / BK;            // 8

    const int ar0 = tid >> 2;
    const int ac  = (tid & 3) * 16;
    const int ack = (tid & 3) * 8;

    const uint32_t aoff = (uint32_t)((wid * 16 + (lane & 15)) * ROWB + (lane >> 4) * 16);
    const uint32_t boff = (uint32_t)(((lane & 7) + ((lane >> 4) << 3)) * ROWB
                                     + ((lane >> 3) & 1) * 16);

    auto issue = [&](int kc) {
        const int k0 = kc * BK;
        uint32_t s = sb + (kc % 3) * STGV;
        cp16(s + ar0 * ROWB + ac,        Asrc + (size_t)(bm + ar0) * NH + k0 + ack);
        cp16(s + (ar0 + 64) * ROWB + ac, Asrc + (size_t)(bm + ar0 + 64) * NH + k0 + ack);
#pragma unroll
        for (int sp = 0; sp < 2; sp++) {
#pragma unroll
            for (int i = 0; i < 2; i++) {
                int slot = tid + 256 * i;
                if (slot < 4 * BNV) {
                    int row = slot >> 2, col16 = (slot & 3) * 16;
                    cp16(s + ATILE + sp * BTILEV + row * ROWB + col16,
                         Bsrc + sp * BSPLIT + (size_t)(bn + row) * NH + k0 + (slot & 3) * 8);
                }
            }
        }
    };

    float acc[10][4];
#pragma unroll
    for (int j = 0; j < 10; j++)
#pragma unroll
        for (int q = 0; q < 4; q++) acc[j][q] = 0.0f;

    issue(0); CP_COMMIT();
    issue(1); CP_COMMIT();

#pragma unroll 1
    for (int kc = 0; kc < nk; kc++) {
        CP_WAIT(1);
        __syncthreads();
        if (kc + 2 < nk) issue(kc + 2);
        CP_COMMIT();

        const uint32_t sA = sb + (kc % 3) * STGV;
        const uint32_t sB = sA + ATILE;
#pragma unroll
        for (int ks = 0; ks < 2; ks++) {
            uint32_t a[4];
            ldmx4(a, sA + aoff + (uint32_t)(ks * 32));
#pragma unroll
            for (int sp = 0; sp < 2; sp++) {
#pragma unroll
                for (int g = 0; g < 5; g++) {
                    uint32_t b[4];
                    ldmx4(b, sB + sp * BTILEV + boff
                             + (uint32_t)(g * 16 * ROWB + ks * 32));
                    mma16816(acc[g * 2 + 0], a, b[0], b[1]);
                    mma16816(acc[g * 2 + 1], a, b[2], b[3]);
                }
            }
        }
    }

    // ---- epilogue: acc -> smem fp32 tile -> argmax(logit + preloaded gumbel) ----
    __syncthreads();
    const int r4 = lane >> 2;
    const int c2 = (lane & 3) * 2;
    const int rw = wid * 16 + r4;
#pragma unroll
    for (int g = 0; g < 10; g++) {
        int col = g * 8 + c2;
        *(float2*)(tile + rw * TS + col)       = make_float2(acc[g][0], acc[g][1]);
        *(float2*)(tile + (rw + 8) * TS + col) = make_float2(acc[g][2], acc[g][3]);
    }
    __syncthreads();

    const int v0g = blockIdx.x * 16;
#pragma unroll 1
    for (int j = 0; j < 8; j++) {
        int idx = tid + 256 * j;
        int r  = idx >> 4;
        int vl = idx & 15;
        int bg = bm + r;
        int vg = v0g + vl;
        float best = 0.0f;
        uint32_t bc = 0;
#pragma unroll
        for (int c = 0; c < NC; c++) {
            float l = __fadd_rn(tile[r * TS + vl * NC + c], bvec[c * NV + vg]);
            float gmb = g_gn[(size_t)bg * NCV + c * NV + vg];
            float s = __fadd_rn(gmb, l);
            if (c == 0 || s > best) { best = s; bc = (uint32_t)c; }
        }
#pragma unroll
        for (int c = 0; c < NC; c++)
            g_A[(size_t)bg * NCV + c * NV + vg] =
                __ushort_as_half((c == (int)bc) ? (unsigned short)0x3C00u : (unsigned short)0u);
        if (WRITE_OUT) {
#pragma unroll
            for (int c = 0; c < NC; c++)
                vout[(size_t)bg * NCV + c * NV + vg] = (c == (int)bc) ? 1.0f : 0.0f;
        }
    }
}

// ---------------- launcher ----------------
extern "C" void kernel_launch(void* const* d_in, const int* in_sizes, int n_in,
                              void* d_out, int out_size) {
    const float* v0 = (const float*)d_in[0];
    const float* W  = (const float*)d_in[1];
    const float* bb = (const float*)d_in[2];
    const float* cc = (const float*)d_in[3];
    (void)in_sizes; (void)n_in; (void)out_size;

    float* out    = (float*)d_out;
    float* out_v  = out;
    float* out_h  = out + (size_t)NBCV;
    float* out_h0 = out_h + (size_t)NBH;

    // keys = jax.random.split(jax.random.key(42), 5)  (partitionable)
    uint32_t keys[5][2];
    for (uint32_t i = 0; i < 5; i++)
        threefry(0u, 42u, 0u, i, keys[i][0], keys[i][1]);

    cudaFuncSetAttribute(k_mma_h<0>, cudaFuncAttributeMaxDynamicSharedMemorySize, SMEMB);
    cudaFuncSetAttribute(k_mma_h<1>, cudaFuncAttributeMaxDynamicSharedMemorySize, SMEMB);
    cudaFuncSetAttribute(k_mma_v<0>, cudaFuncAttributeMaxDynamicSharedMemorySize, SMEMV);
    cudaFuncSetAttribute(k_mma_v<1>, cudaFuncAttributeMaxDynamicSharedMemorySize, SMEMV);

    void *pA, *pHB, *pWv, *pWh;
    cudaGetSymbolAddress(&pA, g_A);
    cudaGetSymbolAddress(&pHB, g_hb);
    cudaGetSymbolAddress(&pWv, g_Wv2);
    cudaGetSymbolAddress(&pWh, g_Wh2);
    const __half* A   = (const __half*)pA;
    const __half* HB  = (const __half*)pHB;
    const __half* Wv2 = (const __half*)pWv;
    const __half* Wh2 = (const __half*)pWh;

    dim3 gh(NH / BN, NB / BM);      // (4, 128)
    dim3 gv(NCV / BNV, NB / BM);    // (32, 128)

    k_prep_wv<<<NCV * NH / 256, 256>>>(W);
    k_prep_wh<<<dim3(NCV / 256, NH), 256>>>(W);
    k_cast_A0<<<NBCV / 1024, 256>>>(v0);

    // h = sample_h(keys[0], v0) -> out_h0 ; also precompute gumbel(keys[1])
    k_mma_h<1><<<gh, 256, SMEMB>>>(A, Wh2, keys[0][0], keys[0][1],
                                   keys[1][0], keys[1][1], cc, out_h0);
    // iter 0
    k_mma_v<0><<<gv, 256, SMEMV>>>(HB, Wv2, bb, nullptr);
    // sample_h(keys[2]) ; precompute gumbel(keys[3])
    k_mma_h<1><<<gh, 256, SMEMB>>>(A, Wh2, keys[2][0], keys[2][1],
                                   keys[3][0], keys[3][1], cc, nullptr);
    // iter 1
    k_mma_v<1><<<gv, 256, SMEMV>>>(HB, Wv2, bb, out_v);
    // final sample_h(keys[4]) -> out_h (no gumbel precompute)
    k_mma_h<0><<<gh, 256, SMEMB>>>(A, Wh2, keys[4][0], keys[4][1],
                                   0u, 0u, cc, out_h);
}

// round 17
// speedup vs baseline: 1.1534x; 1.1534x over previous
#include <cuda_runtime.h>
#include <cuda_fp16.h>
#include <cstdint>
#include <math.h>

// Problem constants
#define NB 16384
#define NC 5
#define NH 256
#define NV 512
#define NCV 2560
#define NBH 4194304
#define NBCV 41943040u
#define TINYF 1.17549435082228751e-38f

// ---------------- scratch (static device globals) ----------------
__device__ __half g_A[(size_t)NB * NCV];     // one-hot v fp16 (A for sample_h), k = c*512+v
__device__ __half g_hb[(size_t)NB * NH];     // h fp16 (A for sample_v, K=256)
__device__ __half g_Wv2[2][NCV * NH];        // [split][v*5+c][h]   (B for sample_v)
__device__ __half g_Wh2[2][NH * NCV];        // [split][h][c*512+v] (B for sample_h)

// ---------------- threefry2x32 (bit-exact with JAX, partitionable) ----------------
__host__ __device__ __forceinline__ uint32_t rotl32(uint32_t x, int r) {
#ifdef __CUDA_ARCH__
    return __funnelshift_l(x, x, r);
#else
    return (x << r) | (x >> (32 - r));
#endif
}

__host__ __device__ inline void threefry(uint32_t k0, uint32_t k1,
                                         uint32_t x0, uint32_t x1,
                                         uint32_t& o0, uint32_t& o1) {
    uint32_t k2 = k0 ^ k1 ^ 0x1BD11BDAu;
#define TFR(r) { x0 += x1; x1 = rotl32(x1, (r)); x1 ^= x0; }
    x0 += k0; x1 += k1;
    TFR(13) TFR(15) TFR(26) TFR(6)   x0 += k1; x1 += k2 + 1u;
    TFR(17) TFR(29) TFR(16) TFR(24)  x0 += k2; x1 += k0 + 2u;
    TFR(13) TFR(15) TFR(26) TFR(6)   x0 += k0; x1 += k1 + 3u;
    TFR(17) TFR(29) TFR(16) TFR(24)  x0 += k1; x1 += k2 + 4u;
    TFR(13) TFR(15) TFR(26) TFR(6)   x0 += k2; x1 += k0 + 5u;
#undef TFR
    o0 = x0; o1 = x1;
}

__device__ __forceinline__ uint32_t rand_bits(uint32_t k0, uint32_t k1, uint32_t i) {
    uint32_t a, b;
    threefry(k0, k1, 0u, i, a, b);
    return a ^ b;
}

__device__ __forceinline__ float bits_to_unit(uint32_t bits) {
    return __fadd_rn(__uint_as_float((bits >> 9) | 0x3f800000u), -1.0f);
}

// ---------------- small helpers ----------------
__device__ __forceinline__ uint32_t smem_u32(const void* p) {
    uint32_t a;
    asm("{ .reg .u64 t; cvta.to.shared.u64 t, %1; cvt.u32.u64 %0, t; }" : "=r"(a) : "l"(p));
    return a;
}

__device__ __forceinline__ void cp16(uint32_t s, const void* g) {
    asm volatile("cp.async.cg.shared.global [%0], [%1], 16;" :: "r"(s), "l"(g));
}
#define CP_COMMIT() asm volatile("cp.async.commit_group;" ::: "memory")
#define CP_WAIT(n)  asm volatile("cp.async.wait_group %0;" :: "n"(n) : "memory")

__device__ __forceinline__ void ldmx4(uint32_t* r, uint32_t addr) {
    asm volatile("ldmatrix.sync.aligned.m8n8.x4.shared.b16 {%0,%1,%2,%3}, [%4];"
                 : "=r"(r[0]), "=r"(r[1]), "=r"(r[2]), "=r"(r[3]) : "r"(addr));
}

__device__ __forceinline__ void mma16816(float* c, const uint32_t* a,
                                         uint32_t b0, uint32_t b1) {
    asm volatile(
        "mma.sync.aligned.m16n8k16.row.col.f32.f16.f16.f32 "
        "{%0,%1,%2,%3}, {%4,%5,%6,%7}, {%8,%9}, {%0,%1,%2,%3};"
        : "+f"(c[0]), "+f"(c[1]), "+f"(c[2]), "+f"(c[3])
        : "r"(a[0]), "r"(a[1]), "r"(a[2]), "r"(a[3]), "r"(b0), "r"(b1));
}

// ---------------- prep kernels ----------------
__device__ __forceinline__ void split2h(float w, __half& a, __half& b) {
    a = __float2half_rn(w);
    float r1 = w - __half2float(a);
    b = __float2half_rn(r1);
}

// g_Wv2: row index = v*5 + c (argmax-self-contained 80-col tiles)
__global__ void k_prep_wv(const float* __restrict__ W) {
    int i = blockIdx.x * 256 + threadIdx.x;   // over NCV*NH
    int h = i & (NH - 1);
    int row = i >> 8;                         // v*5 + c
    int c = row % NC;
    int v = row / NC;
    __half a, b;
    split2h(W[((size_t)(c * NH + h)) * NV + v], a, b);
    g_Wv2[0][i] = a; g_Wv2[1][i] = b;
}

// g_Wh2: [split][h][cv = c*512+v]
__global__ void k_prep_wh(const float* __restrict__ W) {
    int cv = blockIdx.x * 256 + threadIdx.x;  // 0..2559
    int h  = blockIdx.y;
    int v = cv & (NV - 1);
    int c = cv >> 9;
    __half a, b;
    split2h(W[((size_t)(c * NH + h)) * NV + v], a, b);
    size_t o = (size_t)h * NCV + cv;
    g_Wh2[0][o] = a; g_Wh2[1][o] = b;
}

// g_A = fp16(v0)  (v0 is exact one-hot; layout identical, k = c*512+v)
__global__ void k_cast_A0(const float* __restrict__ v0) {
    size_t i = ((size_t)blockIdx.x * 256 + threadIdx.x) * 4;
    float4 f = *(const float4*)(v0 + i);
    __half o[4] = {__float2half_rn(f.x), __float2half_rn(f.y),
                   __float2half_rn(f.z), __float2half_rn(f.w)};
    *(uint2*)(g_A + i) = *(uint2*)o;
}

// ---------------- shared tiling constants ----------------
#define BM 128
#define BK 32
#define ROWB 80                       // 32 fp16 (64B) + 16B pad -> conflict-free ldmatrix
#define ATILE (BM * ROWB)             // 10240
#define BSPLIT ((size_t)NCV * NH)

// ============ sample_h GEMM: 8 warps x (m16 x n64), 2-stage, occ 4 ============
#define BN 64
#define BTILE (BN * ROWB)             // 5120
#define STG (ATILE + 2 * BTILE)       // 20480
#define SMEMH (2 * STG)               // 40960 -> 4 CTAs/SM by smem

__global__ __launch_bounds__(256, 4)
void k_mma_h(const __half* __restrict__ Asrc,
             const __half* __restrict__ Bsrc,
             uint32_t key0, uint32_t key1,
             const float* __restrict__ cvec,
             float* __restrict__ fout) {
    extern __shared__ char smem[];
    const uint32_t sb = smem_u32(smem);
    const int tid = threadIdx.x;
    const int lane = tid & 31;
    const int wid = tid >> 5;          // 8 warps, each m16 x n64
    const int bn = blockIdx.x * BN;
    const int bm = blockIdx.y * BM;
    const int nk = NCV / BK;           // 80

    const int ar0 = tid >> 2;
    const int ac  = (tid & 3) * 16;
    const int ack = (tid & 3) * 8;
    const int br  = tid >> 2;

    const uint32_t aoff = (uint32_t)((wid * 16 + (lane & 15)) * ROWB + (lane >> 4) * 16);
    const uint32_t boff = (uint32_t)(((lane & 7) + ((lane >> 4) << 3)) * ROWB
                                     + ((lane >> 3) & 1) * 16);

    auto issue = [&](int kc) {
        const int k0 = kc * BK;
        uint32_t s = sb + (kc & 1) * STG;
        cp16(s + ar0 * ROWB + ac,        Asrc + (size_t)(bm + ar0) * NCV + k0 + ack);
        cp16(s + (ar0 + 64) * ROWB + ac, Asrc + (size_t)(bm + ar0 + 64) * NCV + k0 + ack);
#pragma unroll
        for (int sp = 0; sp < 2; sp++)
            cp16(s + ATILE + sp * BTILE + br * ROWB + ac,
                 Bsrc + sp * BSPLIT + (size_t)(bn + br) * NCV + k0 + ack);
    };

    float acc[8][4];                   // 8 n8-frags x 4
#pragma unroll
    for (int j = 0; j < 8; j++)
#pragma unroll
        for (int q = 0; q < 4; q++) acc[j][q] = 0.0f;

    issue(0); CP_COMMIT();

#pragma unroll 1
    for (int kc = 0; kc < nk; kc++) {
        CP_WAIT(0);                    // stage kc loaded
        __syncthreads();               // + all warps done with previous stage
        if (kc + 1 < nk) { issue(kc + 1); CP_COMMIT(); }

        const uint32_t sA = sb + (kc & 1) * STG;
        const uint32_t sB = sA + ATILE;

        // per-accumulator k-order: kc -> ks -> sp  (identical to R9)
#pragma unroll
        for (int ks = 0; ks < 2; ks++) {
            uint32_t a[4];
            ldmx4(a, sA + aoff + (uint32_t)(ks * 32));
#pragma unroll
            for (int sp = 0; sp < 2; sp++) {
#pragma unroll
                for (int nh = 0; nh < 4; nh++) {
                    uint32_t b[4];
                    ldmx4(b, sB + sp * BTILE + boff
                             + (uint32_t)(nh * 16 * ROWB + ks * 32));
                    mma16816(acc[nh * 2 + 0], a, b[0], b[1]);
                    mma16816(acc[nh * 2 + 1], a, b[2], b[3]);
                }
            }
        }
    }

    // epilogue: sigmoid + threefry bernoulli
    const int r4 = lane >> 2;
    const int c2 = (lane & 3) * 2;
#pragma unroll
    for (int ni = 0; ni < 8; ni++) {
        const float* c = acc[ni];
        const int col = bn + ni * 8 + c2;
        const int row = bm + wid * 16 + r4;
        const float cv0 = cvec[col], cv1 = cvec[col + 1];
#pragma unroll
        for (int half_ = 0; half_ < 2; half_++) {
            const int rr = row + half_ * 8;
            float x0 = __fadd_rn(c[half_ * 2 + 0], cv0);
            float x1 = __fadd_rn(c[half_ * 2 + 1], cv1);
            float p0 = __fadd_rn(__fmul_rn(0.5f, tanhf(__fmul_rn(0.5f, x0))), 0.5f);
            float p1 = __fadd_rn(__fmul_rn(0.5f, tanhf(__fmul_rn(0.5f, x1))), 0.5f);
            uint32_t gi = (uint32_t)rr * NH + col;
            float u0 = bits_to_unit(rand_bits(key0, key1, gi));
            float u1 = bits_to_unit(rand_bits(key0, key1, gi + 1));
            uint32_t b0 = (u0 < p0) ? 0x3C00u : 0u;
            uint32_t b1 = (u1 < p1) ? 0x3C00u : 0u;
            *(uint32_t*)(g_hb + (size_t)rr * NH + col) = (b1 << 16) | b0;
            if (fout)
                *(float2*)(fout + (size_t)rr * NH + col) =
                    make_float2(b0 ? 1.0f : 0.0f, b1 ? 1.0f : 0.0f);
        }
    }
}

// ============ sample_v GEMM + fused gumbel-argmax categorical (R9, BN=80) ============
#define BNV 80
#define BTILEV (BNV * ROWB)            // 6400
#define STGV (ATILE + 2 * BTILEV)      // 23040
#define SMEMV (3 * STGV)               // 69120
#define TS 84

template<int WRITE_OUT>
__global__ __launch_bounds__(256, 3)
void k_mma_v(const __half* __restrict__ Asrc,   // g_hb, lda = NH
             const __half* __restrict__ Bsrc,   // g_Wv2, rows v*5+c, ldb = NH
             uint32_t key0, uint32_t key1,
             const float* __restrict__ bvec,
             float* __restrict__ vout) {
    extern __shared__ char smem[];
    const uint32_t sb = smem_u32(smem);
    float* tile = (float*)smem;
    const int tid = threadIdx.x;
    const int lane = tid & 31;
    const int wid = tid >> 5;          // 8 warps, each M=16 rows, full N=80
    const int bn = blockIdx.x * BNV;
    const int bm = blockIdx.y * BM;
    const int nk = NH / BK;            // 8

    const int ar0 = tid >> 2;
    const int ac  = (tid & 3) * 16;
    const int ack = (tid & 3) * 8;

    const uint32_t aoff = (uint32_t)((wid * 16 + (lane & 15)) * ROWB + (lane >> 4) * 16);
    const uint32_t boff = (uint32_t)(((lane & 7) + ((lane >> 4) << 3)) * ROWB
                                     + ((lane >> 3) & 1) * 16);

    auto issue = [&](int kc) {
        const int k0 = kc * BK;
        uint32_t s = sb + (kc % 3) * STGV;
        cp16(s + ar0 * ROWB + ac,        Asrc + (size_t)(bm + ar0) * NH + k0 + ack);
        cp16(s + (ar0 + 64) * ROWB + ac, Asrc + (size_t)(bm + ar0 + 64) * NH + k0 + ack);
#pragma unroll
        for (int sp = 0; sp < 2; sp++) {
#pragma unroll
            for (int i = 0; i < 2; i++) {
                int slot = tid + 256 * i;
                if (slot < 4 * BNV) {
                    int row = slot >> 2, col16 = (slot & 3) * 16;
                    cp16(s + ATILE + sp * BTILEV + row * ROWB + col16,
                         Bsrc + sp * BSPLIT + (size_t)(bn + row) * NH + k0 + (slot & 3) * 8);
                }
            }
        }
    };

    float acc[10][4];
#pragma unroll
    for (int j = 0; j < 10; j++)
#pragma unroll
        for (int q = 0; q < 4; q++) acc[j][q] = 0.0f;

    issue(0); CP_COMMIT();
    issue(1); CP_COMMIT();

#pragma unroll 1
    for (int kc = 0; kc < nk; kc++) {
        CP_WAIT(1);
        __syncthreads();
        if (kc + 2 < nk) issue(kc + 2);
        CP_COMMIT();

        const uint32_t sA = sb + (kc % 3) * STGV;
        const uint32_t sB = sA + ATILE;
#pragma unroll
        for (int ks = 0; ks < 2; ks++) {
            uint32_t a[4];
            ldmx4(a, sA + aoff + (uint32_t)(ks * 32));
#pragma unroll
            for (int sp = 0; sp < 2; sp++) {
#pragma unroll
                for (int g = 0; g < 5; g++) {
                    uint32_t b[4];
                    ldmx4(b, sB + sp * BTILEV + boff
                             + (uint32_t)(g * 16 * ROWB + ks * 32));
                    mma16816(acc[g * 2 + 0], a, b[0], b[1]);
                    mma16816(acc[g * 2 + 1], a, b[2], b[3]);
                }
            }
        }
    }

    // ---- epilogue: acc -> smem fp32 tile -> gumbel argmax over c ----
    __syncthreads();
    const int r4 = lane >> 2;
    const int c2 = (lane & 3) * 2;
    const int rw = wid * 16 + r4;
#pragma unroll
    for (int g = 0; g < 10; g++) {
        int col = g * 8 + c2;
        *(float2*)(tile + rw * TS + col)       = make_float2(acc[g][0], acc[g][1]);
        *(float2*)(tile + (rw + 8) * TS + col) = make_float2(acc[g][2], acc[g][3]);
    }
    __syncthreads();

    const int v0g = blockIdx.x * 16;
#pragma unroll 1
    for (int j = 0; j < 8; j++) {
        int idx = tid + 256 * j;
        int r  = idx >> 4;
        int vl = idx & 15;
        int bg = bm + r;
        int vg = v0g + vl;
        float best = 0.0f;
        uint32_t bc = 0;
#pragma unroll
        for (int c = 0; c < NC; c++) {
            float l = __fadd_rn(tile[r * TS + vl * NC + c], bvec[c * NV + vg]);
            uint32_t gi = (((uint32_t)bg * NC + (uint32_t)c) << 9) + (uint32_t)vg;
            float u = bits_to_unit(rand_bits(key0, key1, gi));
            float up = fmaxf(__fadd_rn(u, TINYF), TINYF);
            float gmb = -logf(-logf(up));
            float s = __fadd_rn(gmb, l);
            if (c == 0 || s > best) { best = s; bc = (uint32_t)c; }
        }
#pragma unroll
        for (int c = 0; c < NC; c++)
            g_A[(size_t)bg * NCV + c * NV + vg] =
                __ushort_as_half((c == (int)bc) ? (unsigned short)0x3C00u : (unsigned short)0u);
        if (WRITE_OUT) {
#pragma unroll
            for (int c = 0; c < NC; c++)
                vout[(size_t)bg * NCV + c * NV + vg] = (c == (int)bc) ? 1.0f : 0.0f;
        }
    }
}

// ---------------- launcher ----------------
extern "C" void kernel_launch(void* const* d_in, const int* in_sizes, int n_in,
                              void* d_out, int out_size) {
    const float* v0 = (const float*)d_in[0];
    const float* W  = (const float*)d_in[1];
    const float* bb = (const float*)d_in[2];
    const float* cc = (const float*)d_in[3];
    (void)in_sizes; (void)n_in; (void)out_size;

    float* out    = (float*)d_out;
    float* out_v  = out;
    float* out_h  = out + (size_t)NBCV;
    float* out_h0 = out_h + (size_t)NBH;

    // keys = jax.random.split(jax.random.key(42), 5)  (partitionable)
    uint32_t keys[5][2];
    for (uint32_t i = 0; i < 5; i++)
        threefry(0u, 42u, 0u, i, keys[i][0], keys[i][1]);

    cudaFuncSetAttribute(k_mma_h,    cudaFuncAttributeMaxDynamicSharedMemorySize, SMEMH);
    cudaFuncSetAttribute(k_mma_v<0>, cudaFuncAttributeMaxDynamicSharedMemorySize, SMEMV);
    cudaFuncSetAttribute(k_mma_v<1>, cudaFuncAttributeMaxDynamicSharedMemorySize, SMEMV);

    void *pA, *pHB, *pWv, *pWh;
    cudaGetSymbolAddress(&pA, g_A);
    cudaGetSymbolAddress(&pHB, g_hb);
    cudaGetSymbolAddress(&pWv, g_Wv2);
    cudaGetSymbolAddress(&pWh, g_Wh2);
    const __half* A   = (const __half*)pA;
    const __half* HB  = (const __half*)pHB;
    const __half* Wv2 = (const __half*)pWv;
    const __half* Wh2 = (const __half*)pWh;

    dim3 gh(NH / BN, NB / BM);      // (4, 128)
    dim3 gv(NCV / BNV, NB / BM);    // (32, 128)

    k_prep_wv<<<NCV * NH / 256, 256>>>(W);
    k_prep_wh<<<dim3(NCV / 256, NH), 256>>>(W);
    k_cast_A0<<<NBCV / 1024, 256>>>(v0);

    // h = sample_h(keys[0], v0) -> out_h0
    k_mma_h<<<gh, 256, SMEMH>>>(A, Wh2, keys[0][0], keys[0][1], cc, out_h0);
    // iter 0
    k_mma_v<0><<<gv, 256, SMEMV>>>(HB, Wv2, keys[1][0], keys[1][1], bb, nullptr);
    k_mma_h<<<gh, 256, SMEMH>>>(A, Wh2, keys[2][0], keys[2][1], cc, nullptr);
    // iter 1
    k_mma_v<1><<<gv, 256, SMEMV>>>(HB, Wv2, keys[3][0], keys[3][1], bb, out_v);
    k_mma_h<<<gh, 256, SMEMH>>>(A, Wh2, keys[4][0], keys[4][1], cc, out_h);
}